// round 1
// baseline (speedup 1.0000x reference)
#include <cuda_runtime.h>
#include <math.h>

// Problem constants (fixed by the reference)
#define T  1024      // S*B tokens
#define H  1024      // hidden
#define II 2816      // intermediate
#define E  8         // experts

#define TM 64
#define TN 64
#define BK 32

// ---------------- scratch (no allocations allowed) ----------------
__device__ int   g_expert_id[T];
__device__ int   g_counts[E];
__device__ int   g_offsets[E + 1];
__device__ int   g_cursor[E];
__device__ int   g_token_list[T];
__device__ float g_act[(size_t)T * II];   // silu(g)*u, grouped-by-expert row order

// ---------------- tiny setup kernels ----------------
__global__ void zero_kernel() {
    int i = threadIdx.x;
    if (i < E) { g_counts[i] = 0; g_cursor[i] = 0; }
}

// One block per token. 8 warps -> 8 experts. Strict '>' argmax == jnp.argmax first-max.
__global__ void router_kernel(const float* __restrict__ x, const float* __restrict__ rw) {
    int t = blockIdx.x;
    __shared__ float sx[H];
    for (int i = threadIdx.x; i < H; i += blockDim.x) sx[i] = x[(size_t)t * H + i];
    __syncthreads();
    int w = threadIdx.x >> 5, l = threadIdx.x & 31;
    const float* wr = rw + (size_t)w * H;
    float acc = 0.f;
    for (int i = l; i < H; i += 32) acc += sx[i] * wr[i];
#pragma unroll
    for (int o = 16; o > 0; o >>= 1) acc += __shfl_xor_sync(0xffffffffu, acc, o);
    __shared__ float logits[E];
    if (l == 0) logits[w] = acc;
    __syncthreads();
    if (threadIdx.x == 0) {
        int best = 0; float bv = logits[0];
#pragma unroll
        for (int e = 1; e < E; e++) { if (logits[e] > bv) { bv = logits[e]; best = e; } }
        g_expert_id[t] = best;
        atomicAdd(&g_counts[best], 1);
    }
}

__global__ void scan_kernel() {
    if (threadIdx.x == 0) {
        int o = 0;
        for (int e = 0; e < E; e++) { g_offsets[e] = o; o += g_counts[e]; }
        g_offsets[E] = o;
    }
}

__global__ void scatter_kernel() {
    int t = blockIdx.x * blockDim.x + threadIdx.x;
    if (t < T) {
        int e = g_expert_id[t];
        int p = g_offsets[e] + atomicAdd(&g_cursor[e], 1);
        g_token_list[p] = t;
    }
}

// ---------------- grouped GEMM 1: act = silu(X Wg^T) * (X Wu^T) ----------------
// grid: (II/TN, T/TM, E). Block tile: TM tokens x TN intermediate, K = H.
__global__ __launch_bounds__(256, 2)
void gateup_kernel(const float* __restrict__ x,
                   const float* __restrict__ gw,
                   const float* __restrict__ uw) {
    int e   = blockIdx.z;
    int off = g_offsets[e];
    int n   = g_offsets[e + 1] - off;
    int t0  = blockIdx.y * TM;
    if (t0 >= n) return;
    int i0  = blockIdx.x * TN;

    __shared__ float sX[TM][36];   // [m][k], pad keeps stores conflict-free & f4-aligned
    __shared__ float sG[BK][68];   // [k][n], pad 68 keeps f4-aligned rows
    __shared__ float sU[BK][68];

    int tid = threadIdx.x;
    int tx = tid & 15, ty = tid >> 4;
    int mb = ty * 4, nb = tx * 4;

    int lr = tid >> 3;          // 0..31 (load row)
    int lk = (tid & 7) * 4;     // 0..28 (load k, float4)

    const float* xr[2];
#pragma unroll
    for (int h = 0; h < 2; h++) {
        int gm = t0 + lr + h * 32;
        xr[h] = (gm < n) ? (x + (size_t)g_token_list[off + gm] * H) : (const float*)0;
    }
    const float* gwe = gw + (size_t)e * II * H;
    const float* uwe = uw + (size_t)e * II * H;

    float ag[4][4], au[4][4];
#pragma unroll
    for (int i = 0; i < 4; i++)
#pragma unroll
        for (int j = 0; j < 4; j++) { ag[i][j] = 0.f; au[i][j] = 0.f; }

    for (int k0 = 0; k0 < H; k0 += BK) {
#pragma unroll
        for (int h = 0; h < 2; h++) {
            float4 v = make_float4(0.f, 0.f, 0.f, 0.f);
            if (xr[h]) v = *(const float4*)(xr[h] + k0 + lk);
            *(float4*)&sX[lr + h * 32][lk] = v;
        }
#pragma unroll
        for (int h = 0; h < 2; h++) {
            int row = lr + h * 32;                       // 0..63 within i-tile
            float4 gv = *(const float4*)(gwe + (size_t)(i0 + row) * H + k0 + lk);
            float4 uv = *(const float4*)(uwe + (size_t)(i0 + row) * H + k0 + lk);
            sG[lk + 0][row] = gv.x; sG[lk + 1][row] = gv.y;
            sG[lk + 2][row] = gv.z; sG[lk + 3][row] = gv.w;
            sU[lk + 0][row] = uv.x; sU[lk + 1][row] = uv.y;
            sU[lk + 2][row] = uv.z; sU[lk + 3][row] = uv.w;
        }
        __syncthreads();
#pragma unroll
        for (int kk = 0; kk < BK; kk++) {
            float a[4];
#pragma unroll
            for (int j = 0; j < 4; j++) a[j] = sX[mb + j][kk];
            float4 bg = *(const float4*)&sG[kk][nb];
            float4 bu = *(const float4*)&sU[kk][nb];
#pragma unroll
            for (int j = 0; j < 4; j++) {
                ag[j][0] += a[j] * bg.x; ag[j][1] += a[j] * bg.y;
                ag[j][2] += a[j] * bg.z; ag[j][3] += a[j] * bg.w;
                au[j][0] += a[j] * bu.x; au[j][1] += a[j] * bu.y;
                au[j][2] += a[j] * bu.z; au[j][3] += a[j] * bu.w;
            }
        }
        __syncthreads();
    }
#pragma unroll
    for (int j = 0; j < 4; j++) {
        int gm = t0 + mb + j;
        if (gm < n) {
            float4 o;
            float g;
            g = ag[j][0]; o.x = (g / (1.f + expf(-g))) * au[j][0];
            g = ag[j][1]; o.y = (g / (1.f + expf(-g))) * au[j][1];
            g = ag[j][2]; o.z = (g / (1.f + expf(-g))) * au[j][2];
            g = ag[j][3]; o.w = (g / (1.f + expf(-g))) * au[j][3];
            *(float4*)&g_act[(size_t)(off + gm) * II + i0 + nb] = o;
        }
    }
}

// ---------------- grouped GEMM 2: out[token] = act @ Wd^T ----------------
// grid: (H/TN, T/TM, E). Block tile: TM tokens x TN hidden, K = II.
__global__ __launch_bounds__(256, 2)
void down_kernel(const float* __restrict__ dw, float* __restrict__ out) {
    int e   = blockIdx.z;
    int off = g_offsets[e];
    int n   = g_offsets[e + 1] - off;
    int t0  = blockIdx.y * TM;
    if (t0 >= n) return;
    int h0  = blockIdx.x * TN;

    __shared__ float sA[TM][36];
    __shared__ float sW[BK][68];

    int tid = threadIdx.x;
    int tx = tid & 15, ty = tid >> 4;
    int mb = ty * 4, nb = tx * 4;
    int lr = tid >> 3;
    int lk = (tid & 7) * 4;

    const float* dwe = dw + (size_t)e * H * II;

    float acc[4][4];
#pragma unroll
    for (int i = 0; i < 4; i++)
#pragma unroll
        for (int j = 0; j < 4; j++) acc[i][j] = 0.f;

    for (int k0 = 0; k0 < II; k0 += BK) {
#pragma unroll
        for (int h = 0; h < 2; h++) {
            int gm = t0 + lr + h * 32;
            float4 v = make_float4(0.f, 0.f, 0.f, 0.f);
            if (gm < n) v = *(const float4*)&g_act[(size_t)(off + gm) * II + k0 + lk];
            *(float4*)&sA[lr + h * 32][lk] = v;
        }
#pragma unroll
        for (int h = 0; h < 2; h++) {
            int row = lr + h * 32;                        // 0..63 within h-tile
            float4 wv = *(const float4*)(dwe + (size_t)(h0 + row) * II + k0 + lk);
            sW[lk + 0][row] = wv.x; sW[lk + 1][row] = wv.y;
            sW[lk + 2][row] = wv.z; sW[lk + 3][row] = wv.w;
        }
        __syncthreads();
#pragma unroll
        for (int kk = 0; kk < BK; kk++) {
            float a[4];
#pragma unroll
            for (int j = 0; j < 4; j++) a[j] = sA[mb + j][kk];
            float4 b = *(const float4*)&sW[kk][nb];
#pragma unroll
            for (int j = 0; j < 4; j++) {
                acc[j][0] += a[j] * b.x; acc[j][1] += a[j] * b.y;
                acc[j][2] += a[j] * b.z; acc[j][3] += a[j] * b.w;
            }
        }
        __syncthreads();
    }
#pragma unroll
    for (int j = 0; j < 4; j++) {
        int gm = t0 + mb + j;
        if (gm < n) {
            int tok = g_token_list[off + gm];
            float4 o = make_float4(acc[j][0], acc[j][1], acc[j][2], acc[j][3]);
            *(float4*)&out[(size_t)tok * H + h0 + nb] = o;
        }
    }
}

// ---------------- launch ----------------
extern "C" void kernel_launch(void* const* d_in, const int* in_sizes, int n_in,
                              void* d_out, int out_size) {
    const float* x  = (const float*)d_in[0];   // hidden_states [S,B,H] == [T,H]
    const float* rw = (const float*)d_in[1];   // router_w [E,H]
    const float* gw = (const float*)d_in[2];   // gate_w [E,II,H]
    const float* uw = (const float*)d_in[3];   // up_w   [E,II,H]
    const float* dw = (const float*)d_in[4];   // down_w [E,H,II]
    float* out = (float*)d_out;                // [T,H]

    zero_kernel<<<1, 32>>>();
    router_kernel<<<T, 256>>>(x, rw);
    scan_kernel<<<1, 32>>>();
    scatter_kernel<<<4, 256>>>();
    gateup_kernel<<<dim3(II / TN, T / TM, E), 256>>>(x, gw, uw);
    down_kernel<<<dim3(H / TN, T / TM, E), 256>>>(dw, out);
}